// round 7
// baseline (speedup 1.0000x reference)
#include <cuda_runtime.h>
#include <cuda_bf16.h>
#include <cmath>

// Problem constants (fixed by the reference)
#define B_SZ     2
#define L_SZ     2048
#define D_MODEL  1024
#define D_INNER  2048
#define D_STATE  16
#define D_CONV   4
#define M_ROWS   (B_SZ * L_SZ)        // 4096 flattened rows
#define XZ_COLS  (2 * D_INNER)        // 4096
#define NPROJ    (1 + 2 * D_STATE)    // 33

// ---------------- scratch (device globals; no allocation allowed) -----------
__device__ float g_xz[(size_t)M_ROWS * XZ_COLS];      // 67 MB: [m][4096] (x_in | z)
__device__ float g_xconv[(size_t)M_ROWS * D_INNER];   // 33.5 MB
__device__ float g_ssmin[(size_t)M_ROWS * NPROJ];     // 0.54 MB: [m][33] = dt | B(16) | C(16)
__device__ float g_y[(size_t)M_ROWS * D_INNER];       // 33.5 MB

// ---------------- fp32 SGEMM: C[M][N] = A[M][K] * B[N][K]^T -----------------
// BM=BN=128, BK=16, 256 threads, 8x8 per thread. All dims divide exactly here.
#define BM 128
#define BN 128
#define BK 16
#define TM 8
#define TN 8

__global__ __launch_bounds__(256, 2)
void sgemm_nt(const float* __restrict__ A, const float* __restrict__ B,
              float* __restrict__ C, int M, int N, int K) {
    __shared__ float As[BK][BM];
    __shared__ float Bs[BK][BN];
    const int tid = threadIdx.x;
    const int tx = tid % 16;
    const int ty = tid / 16;
    const int row0 = blockIdx.y * BM;
    const int col0 = blockIdx.x * BN;

    float acc[TM][TN];
#pragma unroll
    for (int i = 0; i < TM; i++)
#pragma unroll
        for (int j = 0; j < TN; j++) acc[i][j] = 0.f;

    const int lrow = tid / 4;         // 0..63
    const int lcol = (tid % 4) * 4;   // 0,4,8,12

    for (int k0 = 0; k0 < K; k0 += BK) {
#pragma unroll
        for (int r = 0; r < 2; r++) {
            const int mm = lrow + r * 64;
            float4 va = *(const float4*)(A + (size_t)(row0 + mm) * K + k0 + lcol);
            As[lcol + 0][mm] = va.x; As[lcol + 1][mm] = va.y;
            As[lcol + 2][mm] = va.z; As[lcol + 3][mm] = va.w;
            float4 vb = *(const float4*)(B + (size_t)(col0 + mm) * K + k0 + lcol);
            Bs[lcol + 0][mm] = vb.x; Bs[lcol + 1][mm] = vb.y;
            Bs[lcol + 2][mm] = vb.z; Bs[lcol + 3][mm] = vb.w;
        }
        __syncthreads();
#pragma unroll
        for (int k = 0; k < BK; k++) {
            float ra[TM], rb[TN];
#pragma unroll
            for (int i = 0; i < TM; i += 4) {
                float4 v = *(const float4*)&As[k][ty * TM + i];
                ra[i] = v.x; ra[i + 1] = v.y; ra[i + 2] = v.z; ra[i + 3] = v.w;
            }
#pragma unroll
            for (int j = 0; j < TN; j += 4) {
                float4 v = *(const float4*)&Bs[k][tx * TN + j];
                rb[j] = v.x; rb[j + 1] = v.y; rb[j + 2] = v.z; rb[j + 3] = v.w;
            }
#pragma unroll
            for (int i = 0; i < TM; i++)
#pragma unroll
                for (int j = 0; j < TN; j++)
                    acc[i][j] = fmaf(ra[i], rb[j], acc[i][j]);
        }
        __syncthreads();
    }

#pragma unroll
    for (int i = 0; i < TM; i++) {
        float* crow = C + (size_t)(row0 + ty * TM + i) * N + col0 + tx * TN;
#pragma unroll
        for (int j = 0; j < TN; j += 4) {
            float4 v = make_float4(acc[i][j], acc[i][j + 1], acc[i][j + 2], acc[i][j + 3]);
            *(float4*)(crow + j) = v;
        }
    }
}

// ---------------- depthwise causal conv(4) + bias + SiLU --------------------
// thread = (b, l-chunk, d); sliding 4-tap window in registers; coalesced in d.
__global__ void conv_silu_kernel(const float* __restrict__ conv_w,
                                 const float* __restrict__ conv_b) {
    const int d  = blockIdx.x * blockDim.x + threadIdx.x;  // 0..2047
    const int l0 = blockIdx.y * 128;
    const int b  = blockIdx.z;

    const float w0 = conv_w[d * 4 + 0];
    const float w1 = conv_w[d * 4 + 1];
    const float w2 = conv_w[d * 4 + 2];
    const float w3 = conv_w[d * 4 + 3];
    const float bias = conv_b[d];

    const float* xin = g_xz + (size_t)b * L_SZ * XZ_COLS + d;   // x_in = cols [0,2048)
    float* out = g_xconv + ((size_t)b * L_SZ + l0) * D_INNER + d;

    float s0 = (l0 - 3 >= 0) ? xin[(size_t)(l0 - 3) * XZ_COLS] : 0.f;
    float s1 = (l0 - 2 >= 0) ? xin[(size_t)(l0 - 2) * XZ_COLS] : 0.f;
    float s2 = (l0 - 1 >= 0) ? xin[(size_t)(l0 - 1) * XZ_COLS] : 0.f;

    for (int i = 0; i < 128; i++) {
        float s3 = xin[(size_t)(l0 + i) * XZ_COLS];
        float v = fmaf(w0, s0, fmaf(w1, s1, fmaf(w2, s2, fmaf(w3, s3, bias))));
        float sig = 1.f / (1.f + __expf(-v));
        out[(size_t)i * D_INNER] = v * sig;
        s0 = s1; s1 = s2; s2 = s3;
    }
}

// ---------------- x-projection: ssm_in[m][33] = x_conv[m] @ W_xproj^T -------
// 4 rows per block staged in smem; 8 warps each cover n = w, w+8, ...
__global__ void xproj_kernel(const float* __restrict__ Wx) {
    __shared__ float xs[4][D_INNER];
    const int m0 = blockIdx.x * 4;
    const int tid = threadIdx.x;   // 256

    for (int r = 0; r < 4; r++)
        for (int k = tid; k < D_INNER; k += 256)
            xs[r][k] = g_xconv[(size_t)(m0 + r) * D_INNER + k];
    __syncthreads();

    const int w = tid / 32, lane = tid % 32;
    for (int n = w; n < NPROJ; n += 8) {
        const float* wrow = Wx + (size_t)n * D_INNER;
#pragma unroll
        for (int r = 0; r < 4; r++) {
            float s = 0.f;
            for (int k = lane; k < D_INNER; k += 32)
                s = fmaf(xs[r][k], wrow[k], s);
#pragma unroll
            for (int o = 16; o > 0; o >>= 1)
                s += __shfl_xor_sync(0xffffffffu, s, o);
            if (lane == 0) g_ssmin[(size_t)(m0 + r) * NPROJ + n] = s;
        }
    }
}

// ---------------- selective scan + gating ----------------------------------
// thread = (b, d, s); 16 lanes per channel; delta computed on the fly (rank-1
// softplus) so the 67MB delta tensor is never materialized. 16-lane shfl
// reduction of h*C; lane s==0 applies +x_conv*D and *silu(z) and writes y.
// Grid: (B_SZ * D_INNER) / 16 = 256 blocks of 256 threads (16 channels/block).
__global__ void scan_kernel(const float* __restrict__ A_log,
                            const float* __restrict__ W_dt,
                            const float* __restrict__ b_dt,
                            const float* __restrict__ Dvec) {
    const int tid = threadIdx.x;
    const int s  = tid & 15;
    const int ch = tid >> 4;                  // 0..15 channels per block
    const int c  = blockIdx.x * 16 + ch;      // global channel 0..(B_SZ*D_INNER-1)
    const int b  = c >> 11;                   // / D_INNER
    const int d  = c & (D_INNER - 1);

    const float Av  = -expf(A_log[d * D_STATE + s]);
    const float wdt = W_dt[d];
    const float bdt = b_dt[d];
    const float Dd  = Dvec[d];

    const float* sr  = g_ssmin + (size_t)b * L_SZ * NPROJ;
    const float* xcp = g_xconv + (size_t)b * L_SZ * D_INNER + d;
    const float* zp  = g_xz    + (size_t)b * L_SZ * XZ_COLS + D_INNER + d;
    float*       yp  = g_y     + (size_t)b * L_SZ * D_INNER + d;

    float h = 0.f;
    for (int l = 0; l < L_SZ; l++) {
        const float* row = sr + (size_t)l * NPROJ;
        const float dtr = row[0];
        const float Bv  = row[1 + s];
        const float Cv  = row[1 + D_STATE + s];
        const float xcv = xcp[(size_t)l * D_INNER];

        float u = fmaf(dtr, wdt, bdt);
        float delta = (u > 20.f) ? u : log1pf(__expf(u));
        float dA = __expf(delta * Av);
        h = fmaf(dA, h, delta * Bv * xcv);

        float p = h * Cv;
        p += __shfl_xor_sync(0xffffffffu, p, 8);
        p += __shfl_xor_sync(0xffffffffu, p, 4);
        p += __shfl_xor_sync(0xffffffffu, p, 2);
        p += __shfl_xor_sync(0xffffffffu, p, 1);

        if (s == 0) {
            float zv = zp[(size_t)l * XZ_COLS];
            float sig = 1.f / (1.f + __expf(-zv));
            yp[(size_t)l * D_INNER] = (p + xcv * Dd) * (zv * sig);
        }
    }
}

// ---------------- launch ----------------------------------------------------
extern "C" void kernel_launch(void* const* d_in, const int* in_sizes, int n_in,
                              void* d_out, int out_size) {
    const float* x      = (const float*)d_in[0];
    const float* W_in   = (const float*)d_in[1];
    const float* conv_w = (const float*)d_in[2];
    const float* conv_b = (const float*)d_in[3];
    const float* W_xp   = (const float*)d_in[4];
    const float* W_dt   = (const float*)d_in[5];
    const float* b_dt   = (const float*)d_in[6];
    const float* A_log  = (const float*)d_in[7];
    const float* Dv     = (const float*)d_in[8];
    const float* W_out  = (const float*)d_in[9];
    float* out = (float*)d_out;

    float *xz = nullptr, *yb = nullptr;
    cudaGetSymbolAddress((void**)&xz, g_xz);
    cudaGetSymbolAddress((void**)&yb, g_y);

    // 1) in-projection: xz[4096][4096] = x[4096][1024] @ W_in[4096][1024]^T
    sgemm_nt<<<dim3(XZ_COLS / BN, M_ROWS / BM), 256>>>(x, W_in, xz,
                                                       M_ROWS, XZ_COLS, D_MODEL);
    // 2) depthwise conv + SiLU
    conv_silu_kernel<<<dim3(D_INNER / 256, L_SZ / 128, B_SZ), 256>>>(conv_w, conv_b);
    // 3) x-projection (dt | B | C)
    xproj_kernel<<<M_ROWS / 4, 256>>>(W_xp);
    // 4) selective scan + D skip + SiLU(z) gate
    //    channels = B_SZ * D_INNER = 4096; 16 channels/block -> 256 blocks
    scan_kernel<<<(B_SZ * D_INNER) / 16, 256>>>(A_log, W_dt, b_dt, Dv);
    // 5) out-projection: out[4096][1024] = y[4096][2048] @ W_out[1024][2048]^T
    sgemm_nt<<<dim3(D_MODEL / BN, M_ROWS / BM), 256>>>(yb, W_out, out,
                                                       M_ROWS, D_MODEL, D_INNER);
}

// round 9
// speedup vs baseline: 1.0039x; 1.0039x over previous
#include <cuda_runtime.h>
#include <cuda_bf16.h>
#include <cmath>

// Problem constants (fixed by the reference)
#define B_SZ     2
#define L_SZ     2048
#define D_MODEL  1024
#define D_INNER  2048
#define D_STATE  16
#define D_CONV   4
#define M_ROWS   (B_SZ * L_SZ)        // 4096 flattened rows
#define XZ_COLS  (2 * D_INNER)        // 4096
#define NPROJ    (1 + 2 * D_STATE)    // 33

// ---------------- scratch (device globals; no allocation allowed) -----------
__device__ float g_xz[(size_t)M_ROWS * XZ_COLS];      // 67 MB: [m][4096] (x_in | z)
__device__ float g_xconv[(size_t)M_ROWS * D_INNER];   // 33.5 MB
__device__ float g_ssmin[(size_t)M_ROWS * NPROJ];     // 0.54 MB: [m][33] = dt | B(16) | C(16)
__device__ float g_y[(size_t)M_ROWS * D_INNER];       // 33.5 MB

// ---------------- fp32 SGEMM: C[M][N] = A[M][K] * B[N][K]^T -----------------
// BM=BN=128, BK=16, 256 threads, 8x8 per thread. All dims divide exactly here.
#define BM 128
#define BN 128
#define BK 16
#define TM 8
#define TN 8

__global__ __launch_bounds__(256, 2)
void sgemm_nt(const float* __restrict__ A, const float* __restrict__ B,
              float* __restrict__ C, int M, int N, int K) {
    __shared__ float As[BK][BM];
    __shared__ float Bs[BK][BN];
    const int tid = threadIdx.x;
    const int tx = tid % 16;
    const int ty = tid / 16;
    const int row0 = blockIdx.y * BM;
    const int col0 = blockIdx.x * BN;

    float acc[TM][TN];
#pragma unroll
    for (int i = 0; i < TM; i++)
#pragma unroll
        for (int j = 0; j < TN; j++) acc[i][j] = 0.f;

    const int lrow = tid / 4;         // 0..63
    const int lcol = (tid % 4) * 4;   // 0,4,8,12

    for (int k0 = 0; k0 < K; k0 += BK) {
#pragma unroll
        for (int r = 0; r < 2; r++) {
            const int mm = lrow + r * 64;
            float4 va = *(const float4*)(A + (size_t)(row0 + mm) * K + k0 + lcol);
            As[lcol + 0][mm] = va.x; As[lcol + 1][mm] = va.y;
            As[lcol + 2][mm] = va.z; As[lcol + 3][mm] = va.w;
            float4 vb = *(const float4*)(B + (size_t)(col0 + mm) * K + k0 + lcol);
            Bs[lcol + 0][mm] = vb.x; Bs[lcol + 1][mm] = vb.y;
            Bs[lcol + 2][mm] = vb.z; Bs[lcol + 3][mm] = vb.w;
        }
        __syncthreads();
#pragma unroll
        for (int k = 0; k < BK; k++) {
            float ra[TM], rb[TN];
#pragma unroll
            for (int i = 0; i < TM; i += 4) {
                float4 v = *(const float4*)&As[k][ty * TM + i];
                ra[i] = v.x; ra[i + 1] = v.y; ra[i + 2] = v.z; ra[i + 3] = v.w;
            }
#pragma unroll
            for (int j = 0; j < TN; j += 4) {
                float4 v = *(const float4*)&Bs[k][tx * TN + j];
                rb[j] = v.x; rb[j + 1] = v.y; rb[j + 2] = v.z; rb[j + 3] = v.w;
            }
#pragma unroll
            for (int i = 0; i < TM; i++)
#pragma unroll
                for (int j = 0; j < TN; j++)
                    acc[i][j] = fmaf(ra[i], rb[j], acc[i][j]);
        }
        __syncthreads();
    }

#pragma unroll
    for (int i = 0; i < TM; i++) {
        float* crow = C + (size_t)(row0 + ty * TM + i) * N + col0 + tx * TN;
#pragma unroll
        for (int j = 0; j < TN; j += 4) {
            float4 v = make_float4(acc[i][j], acc[i][j + 1], acc[i][j + 2], acc[i][j + 3]);
            *(float4*)(crow + j) = v;
        }
    }
}

// ---------------- depthwise causal conv(4) + bias + SiLU --------------------
// thread = (b, l-chunk, d); sliding 4-tap window in registers; coalesced in d.
__global__ void conv_silu_kernel(const float* __restrict__ conv_w,
                                 const float* __restrict__ conv_b) {
    const int d  = blockIdx.x * blockDim.x + threadIdx.x;  // 0..2047
    const int l0 = blockIdx.y * 128;
    const int b  = blockIdx.z;

    const float w0 = conv_w[d * 4 + 0];
    const float w1 = conv_w[d * 4 + 1];
    const float w2 = conv_w[d * 4 + 2];
    const float w3 = conv_w[d * 4 + 3];
    const float bias = conv_b[d];

    const float* xin = g_xz + (size_t)b * L_SZ * XZ_COLS + d;   // x_in = cols [0,2048)
    float* out = g_xconv + ((size_t)b * L_SZ + l0) * D_INNER + d;

    float s0 = (l0 - 3 >= 0) ? xin[(size_t)(l0 - 3) * XZ_COLS] : 0.f;
    float s1 = (l0 - 2 >= 0) ? xin[(size_t)(l0 - 2) * XZ_COLS] : 0.f;
    float s2 = (l0 - 1 >= 0) ? xin[(size_t)(l0 - 1) * XZ_COLS] : 0.f;

    for (int i = 0; i < 128; i++) {
        float s3 = xin[(size_t)(l0 + i) * XZ_COLS];
        float v = fmaf(w0, s0, fmaf(w1, s1, fmaf(w2, s2, fmaf(w3, s3, bias))));
        float sig = 1.f / (1.f + __expf(-v));
        out[(size_t)i * D_INNER] = v * sig;
        s0 = s1; s1 = s2; s2 = s3;
    }
}

// ---------------- x-projection: ssm_in[m][33] = x_conv[m] @ W_xproj^T -------
// 4 rows per block staged in smem; 8 warps each cover n = w, w+8, ...
__global__ void xproj_kernel(const float* __restrict__ Wx) {
    __shared__ float xs[4][D_INNER];
    const int m0 = blockIdx.x * 4;
    const int tid = threadIdx.x;   // 256

    for (int r = 0; r < 4; r++)
        for (int k = tid; k < D_INNER; k += 256)
            xs[r][k] = g_xconv[(size_t)(m0 + r) * D_INNER + k];
    __syncthreads();

    const int w = tid / 32, lane = tid % 32;
    for (int n = w; n < NPROJ; n += 8) {
        const float* wrow = Wx + (size_t)n * D_INNER;
#pragma unroll
        for (int r = 0; r < 4; r++) {
            float s = 0.f;
            for (int k = lane; k < D_INNER; k += 32)
                s = fmaf(xs[r][k], wrow[k], s);
#pragma unroll
            for (int o = 16; o > 0; o >>= 1)
                s += __shfl_xor_sync(0xffffffffu, s, o);
            if (lane == 0) g_ssmin[(size_t)(m0 + r) * NPROJ + n] = s;
        }
    }
}

// ---------------- selective scan + gating ----------------------------------
// thread = (b, d, s); 16 lanes per channel; delta computed on the fly (rank-1
// softplus) so the 67MB delta tensor is never materialized. 16-lane shfl
// reduction of h*C; lane s==0 applies +x_conv*D and *silu(z) and writes y.
// Grid: (B_SZ * D_INNER) / 16 = 256 blocks of 256 threads (16 channels/block).
__global__ void scan_kernel(const float* __restrict__ A_log,
                            const float* __restrict__ W_dt,
                            const float* __restrict__ b_dt,
                            const float* __restrict__ Dvec) {
    const int tid = threadIdx.x;
    const int s  = tid & 15;
    const int ch = tid >> 4;                  // 0..15 channels per block
    const int c  = blockIdx.x * 16 + ch;      // global channel 0..(B_SZ*D_INNER-1)
    const int b  = c >> 11;                   // / D_INNER
    const int d  = c & (D_INNER - 1);

    const float Av  = -expf(A_log[d * D_STATE + s]);
    const float wdt = W_dt[d];
    const float bdt = b_dt[d];
    const float Dd  = Dvec[d];

    const float* sr  = g_ssmin + (size_t)b * L_SZ * NPROJ;
    const float* xcp = g_xconv + (size_t)b * L_SZ * D_INNER + d;
    const float* zp  = g_xz    + (size_t)b * L_SZ * XZ_COLS + D_INNER + d;
    float*       yp  = g_y     + (size_t)b * L_SZ * D_INNER + d;

    float h = 0.f;
    for (int l = 0; l < L_SZ; l++) {
        const float* row = sr + (size_t)l * NPROJ;
        const float dtr = row[0];
        const float Bv  = row[1 + s];
        const float Cv  = row[1 + D_STATE + s];
        const float xcv = xcp[(size_t)l * D_INNER];

        float u = fmaf(dtr, wdt, bdt);
        float delta = (u > 20.f) ? u : log1pf(__expf(u));
        float dA = __expf(delta * Av);
        h = fmaf(dA, h, delta * Bv * xcv);

        float p = h * Cv;
        p += __shfl_xor_sync(0xffffffffu, p, 8);
        p += __shfl_xor_sync(0xffffffffu, p, 4);
        p += __shfl_xor_sync(0xffffffffu, p, 2);
        p += __shfl_xor_sync(0xffffffffu, p, 1);

        if (s == 0) {
            float zv = zp[(size_t)l * XZ_COLS];
            float sig = 1.f / (1.f + __expf(-zv));
            yp[(size_t)l * D_INNER] = (p + xcv * Dd) * (zv * sig);
        }
    }
}

// ---------------- launch ----------------------------------------------------
extern "C" void kernel_launch(void* const* d_in, const int* in_sizes, int n_in,
                              void* d_out, int out_size) {
    const float* x      = (const float*)d_in[0];
    const float* W_in   = (const float*)d_in[1];
    const float* conv_w = (const float*)d_in[2];
    const float* conv_b = (const float*)d_in[3];
    const float* W_xp   = (const float*)d_in[4];
    const float* W_dt   = (const float*)d_in[5];
    const float* b_dt   = (const float*)d_in[6];
    const float* A_log  = (const float*)d_in[7];
    const float* Dv     = (const float*)d_in[8];
    const float* W_out  = (const float*)d_in[9];
    float* out = (float*)d_out;

    float *xz = nullptr, *yb = nullptr;
    cudaGetSymbolAddress((void**)&xz, g_xz);
    cudaGetSymbolAddress((void**)&yb, g_y);

    // 1) in-projection: xz[4096][4096] = x[4096][1024] @ W_in[4096][1024]^T
    sgemm_nt<<<dim3(XZ_COLS / BN, M_ROWS / BM), 256>>>(x, W_in, xz,
                                                       M_ROWS, XZ_COLS, D_MODEL);
    // 2) depthwise conv + SiLU
    conv_silu_kernel<<<dim3(D_INNER / 256, L_SZ / 128, B_SZ), 256>>>(conv_w, conv_b);
    // 3) x-projection (dt | B | C)
    xproj_kernel<<<M_ROWS / 4, 256>>>(W_xp);
    // 4) selective scan + D skip + SiLU(z) gate
    //    channels = B_SZ * D_INNER = 4096; 16 channels/block -> 256 blocks
    scan_kernel<<<(B_SZ * D_INNER) / 16, 256>>>(A_log, W_dt, b_dt, Dv);
    // 5) out-projection: out[4096][1024] = y[4096][2048] @ W_out[1024][2048]^T
    sgemm_nt<<<dim3(D_MODEL / BN, M_ROWS / BM), 256>>>(yb, W_out, out,
                                                       M_ROWS, D_MODEL, D_INNER);
}

// round 10
// speedup vs baseline: 1.0059x; 1.0020x over previous
#include <cuda_runtime.h>
#include <cuda_bf16.h>
#include <cmath>

// Problem constants (fixed by the reference)
#define B_SZ     2
#define L_SZ     2048
#define D_MODEL  1024
#define D_INNER  2048
#define D_STATE  16
#define D_CONV   4
#define M_ROWS   (B_SZ * L_SZ)        // 4096 flattened rows
#define XZ_COLS  (2 * D_INNER)        // 4096
#define NPROJ    (1 + 2 * D_STATE)    // 33

// ---------------- scratch (device globals; no allocation allowed) -----------
__device__ float g_xz[(size_t)M_ROWS * XZ_COLS];      // 67 MB: [m][4096] (x_in | z)
__device__ float g_xconv[(size_t)M_ROWS * D_INNER];   // 33.5 MB
__device__ float g_ssmin[(size_t)M_ROWS * NPROJ];     // 0.54 MB: [m][33] = dt | B(16) | C(16)
__device__ float g_y[(size_t)M_ROWS * D_INNER];       // 33.5 MB

// ---------------- fp32 SGEMM: C[M][N] = A[M][K] * B[N][K]^T -----------------
// BM=BN=128, BK=16, 256 threads, 8x8 per thread. All dims divide exactly here.
#define BM 128
#define BN 128
#define BK 16
#define TM 8
#define TN 8

__global__ __launch_bounds__(256, 2)
void sgemm_nt(const float* __restrict__ A, const float* __restrict__ B,
              float* __restrict__ C, int M, int N, int K) {
    __shared__ float As[BK][BM];
    __shared__ float Bs[BK][BN];
    const int tid = threadIdx.x;
    const int tx = tid % 16;
    const int ty = tid / 16;
    const int row0 = blockIdx.y * BM;
    const int col0 = blockIdx.x * BN;

    float acc[TM][TN];
#pragma unroll
    for (int i = 0; i < TM; i++)
#pragma unroll
        for (int j = 0; j < TN; j++) acc[i][j] = 0.f;

    const int lrow = tid / 4;         // 0..63
    const int lcol = (tid % 4) * 4;   // 0,4,8,12

    for (int k0 = 0; k0 < K; k0 += BK) {
#pragma unroll
        for (int r = 0; r < 2; r++) {
            const int mm = lrow + r * 64;
            float4 va = *(const float4*)(A + (size_t)(row0 + mm) * K + k0 + lcol);
            As[lcol + 0][mm] = va.x; As[lcol + 1][mm] = va.y;
            As[lcol + 2][mm] = va.z; As[lcol + 3][mm] = va.w;
            float4 vb = *(const float4*)(B + (size_t)(col0 + mm) * K + k0 + lcol);
            Bs[lcol + 0][mm] = vb.x; Bs[lcol + 1][mm] = vb.y;
            Bs[lcol + 2][mm] = vb.z; Bs[lcol + 3][mm] = vb.w;
        }
        __syncthreads();
#pragma unroll
        for (int k = 0; k < BK; k++) {
            float ra[TM], rb[TN];
#pragma unroll
            for (int i = 0; i < TM; i += 4) {
                float4 v = *(const float4*)&As[k][ty * TM + i];
                ra[i] = v.x; ra[i + 1] = v.y; ra[i + 2] = v.z; ra[i + 3] = v.w;
            }
#pragma unroll
            for (int j = 0; j < TN; j += 4) {
                float4 v = *(const float4*)&Bs[k][tx * TN + j];
                rb[j] = v.x; rb[j + 1] = v.y; rb[j + 2] = v.z; rb[j + 3] = v.w;
            }
#pragma unroll
            for (int i = 0; i < TM; i++)
#pragma unroll
                for (int j = 0; j < TN; j++)
                    acc[i][j] = fmaf(ra[i], rb[j], acc[i][j]);
        }
        __syncthreads();
    }

#pragma unroll
    for (int i = 0; i < TM; i++) {
        float* crow = C + (size_t)(row0 + ty * TM + i) * N + col0 + tx * TN;
#pragma unroll
        for (int j = 0; j < TN; j += 4) {
            float4 v = make_float4(acc[i][j], acc[i][j + 1], acc[i][j + 2], acc[i][j + 3]);
            *(float4*)(crow + j) = v;
        }
    }
}

// ---------------- depthwise causal conv(4) + bias + SiLU --------------------
// thread = (b, l-chunk, d); sliding 4-tap window in registers; coalesced in d.
__global__ void conv_silu_kernel(const float* __restrict__ conv_w,
                                 const float* __restrict__ conv_b) {
    const int d  = blockIdx.x * blockDim.x + threadIdx.x;  // 0..2047
    const int l0 = blockIdx.y * 128;
    const int b  = blockIdx.z;

    const float w0 = conv_w[d * 4 + 0];
    const float w1 = conv_w[d * 4 + 1];
    const float w2 = conv_w[d * 4 + 2];
    const float w3 = conv_w[d * 4 + 3];
    const float bias = conv_b[d];

    const float* xin = g_xz + (size_t)b * L_SZ * XZ_COLS + d;   // x_in = cols [0,2048)
    float* out = g_xconv + ((size_t)b * L_SZ + l0) * D_INNER + d;

    float s0 = (l0 - 3 >= 0) ? xin[(size_t)(l0 - 3) * XZ_COLS] : 0.f;
    float s1 = (l0 - 2 >= 0) ? xin[(size_t)(l0 - 2) * XZ_COLS] : 0.f;
    float s2 = (l0 - 1 >= 0) ? xin[(size_t)(l0 - 1) * XZ_COLS] : 0.f;

    for (int i = 0; i < 128; i++) {
        float s3 = xin[(size_t)(l0 + i) * XZ_COLS];
        float v = fmaf(w0, s0, fmaf(w1, s1, fmaf(w2, s2, fmaf(w3, s3, bias))));
        float sig = 1.f / (1.f + __expf(-v));
        out[(size_t)i * D_INNER] = v * sig;
        s0 = s1; s1 = s2; s2 = s3;
    }
}

// ---------------- x-projection: ssm_in[m][33] = x_conv[m] @ W_xproj^T -------
// 4 rows per block staged in smem; 8 warps each cover n = w, w+8, ...
__global__ void xproj_kernel(const float* __restrict__ Wx) {
    __shared__ float xs[4][D_INNER];
    const int m0 = blockIdx.x * 4;
    const int tid = threadIdx.x;   // 256

    for (int r = 0; r < 4; r++)
        for (int k = tid; k < D_INNER; k += 256)
            xs[r][k] = g_xconv[(size_t)(m0 + r) * D_INNER + k];
    __syncthreads();

    const int w = tid / 32, lane = tid % 32;
    for (int n = w; n < NPROJ; n += 8) {
        const float* wrow = Wx + (size_t)n * D_INNER;
#pragma unroll
        for (int r = 0; r < 4; r++) {
            float s = 0.f;
            for (int k = lane; k < D_INNER; k += 32)
                s = fmaf(xs[r][k], wrow[k], s);
#pragma unroll
            for (int o = 16; o > 0; o >>= 1)
                s += __shfl_xor_sync(0xffffffffu, s, o);
            if (lane == 0) g_ssmin[(size_t)(m0 + r) * NPROJ + n] = s;
        }
    }
}

// ---------------- selective scan + gating ----------------------------------
// thread = (b, d, s); 16 lanes per channel; delta computed on the fly (rank-1
// softplus) so the 67MB delta tensor is never materialized. 16-lane shfl
// reduction of h*C; lane s==0 applies +x_conv*D and *silu(z) and writes y.
// Grid: (B_SZ * D_INNER) / 16 = 256 blocks of 256 threads (16 channels/block).
__global__ void scan_kernel(const float* __restrict__ A_log,
                            const float* __restrict__ W_dt,
                            const float* __restrict__ b_dt,
                            const float* __restrict__ Dvec) {
    const int tid = threadIdx.x;
    const int s  = tid & 15;
    const int ch = tid >> 4;                  // 0..15 channels per block
    const int c  = blockIdx.x * 16 + ch;      // global channel 0..(B_SZ*D_INNER-1)
    const int b  = c >> 11;                   // / D_INNER
    const int d  = c & (D_INNER - 1);

    const float Av  = -expf(A_log[d * D_STATE + s]);
    const float wdt = W_dt[d];
    const float bdt = b_dt[d];
    const float Dd  = Dvec[d];

    const float* sr  = g_ssmin + (size_t)b * L_SZ * NPROJ;
    const float* xcp = g_xconv + (size_t)b * L_SZ * D_INNER + d;
    const float* zp  = g_xz    + (size_t)b * L_SZ * XZ_COLS + D_INNER + d;
    float*       yp  = g_y     + (size_t)b * L_SZ * D_INNER + d;

    float h = 0.f;
    for (int l = 0; l < L_SZ; l++) {
        const float* row = sr + (size_t)l * NPROJ;
        const float dtr = row[0];
        const float Bv  = row[1 + s];
        const float Cv  = row[1 + D_STATE + s];
        const float xcv = xcp[(size_t)l * D_INNER];

        float u = fmaf(dtr, wdt, bdt);
        float delta = (u > 20.f) ? u : log1pf(__expf(u));
        float dA = __expf(delta * Av);
        h = fmaf(dA, h, delta * Bv * xcv);

        float p = h * Cv;
        p += __shfl_xor_sync(0xffffffffu, p, 8);
        p += __shfl_xor_sync(0xffffffffu, p, 4);
        p += __shfl_xor_sync(0xffffffffu, p, 2);
        p += __shfl_xor_sync(0xffffffffu, p, 1);

        if (s == 0) {
            float zv = zp[(size_t)l * XZ_COLS];
            float sig = 1.f / (1.f + __expf(-zv));
            yp[(size_t)l * D_INNER] = (p + xcv * Dd) * (zv * sig);
        }
    }
}

// ---------------- launch ----------------------------------------------------
extern "C" void kernel_launch(void* const* d_in, const int* in_sizes, int n_in,
                              void* d_out, int out_size) {
    const float* x      = (const float*)d_in[0];
    const float* W_in   = (const float*)d_in[1];
    const float* conv_w = (const float*)d_in[2];
    const float* conv_b = (const float*)d_in[3];
    const float* W_xp   = (const float*)d_in[4];
    const float* W_dt   = (const float*)d_in[5];
    const float* b_dt   = (const float*)d_in[6];
    const float* A_log  = (const float*)d_in[7];
    const float* Dv     = (const float*)d_in[8];
    const float* W_out  = (const float*)d_in[9];
    float* out = (float*)d_out;

    float *xz = nullptr, *yb = nullptr;
    cudaGetSymbolAddress((void**)&xz, g_xz);
    cudaGetSymbolAddress((void**)&yb, g_y);

    // 1) in-projection: xz[4096][4096] = x[4096][1024] @ W_in[4096][1024]^T
    sgemm_nt<<<dim3(XZ_COLS / BN, M_ROWS / BM), 256>>>(x, W_in, xz,
                                                       M_ROWS, XZ_COLS, D_MODEL);
    // 2) depthwise conv + SiLU
    conv_silu_kernel<<<dim3(D_INNER / 256, L_SZ / 128, B_SZ), 256>>>(conv_w, conv_b);
    // 3) x-projection (dt | B | C)
    xproj_kernel<<<M_ROWS / 4, 256>>>(W_xp);
    // 4) selective scan + D skip + SiLU(z) gate
    //    channels = B_SZ * D_INNER = 4096; 16 channels/block -> 256 blocks
    scan_kernel<<<(B_SZ * D_INNER) / 16, 256>>>(A_log, W_dt, b_dt, Dv);
    // 5) out-projection: out[4096][1024] = y[4096][2048] @ W_out[1024][2048]^T
    sgemm_nt<<<dim3(D_MODEL / BN, M_ROWS / BM), 256>>>(yb, W_out, out,
                                                       M_ROWS, D_MODEL, D_INNER);
}